// round 2
// baseline (speedup 1.0000x reference)
#include <cuda_runtime.h>

// Problem constants
#define HD   160            // H = W = D = 160
#define PLN  25600          // W*D  (one h-plane of one (b) volume)
#define VOL  4096000        // H*W*D
#define NVOX 8192000ULL     // B*C*H*W*D = 2*160^3
#define WT   10             // w-tile width in pass A
#define ROWS 20             // WT + 2*5 halo
#define HSEG 32             // h-segment length in pass B

// Normalized 1D Gaussian, KS=11, sigma=1.5 (symmetric), compile-time constants
__device__ constexpr float GW[11] = {
    0.00102838f, 0.00759876f, 0.03600077f, 0.10936070f, 0.21300553f,
    0.26601172f,
    0.21300553f, 0.10936070f, 0.03600077f, 0.00759876f, 0.00102838f
};

constexpr float C1f  = 1.0e-4f;   // (0.01*1)^2
constexpr float C2f  = 9.0e-4f;   // (0.03*1)^2
constexpr float EPSf = 1.0e-12f;

// Scratch: 5 blurred fields (mu1, mu2, m11, m22, m12), each NVOX floats.
__device__ float  g_buf[5ULL * NVOX];
__device__ double g_acc;

__device__ __forceinline__ int refl(int i) {
    return (i < 0) ? -i : ((i > HD - 1) ? (2 * (HD - 1) - i) : i);
}

// ---------------------------------------------------------------------------
// Pass A: per (b, h, w-tile): load s,r rows [w0-5, w0+WT+5) x D into SMEM,
// blur along D (generating the 5 fields on the fly), blur along W, write the
// 5 intermediates to g_buf.
// Block: 160 threads, tid = d. Dynamic smem: (2 + 5) * ROWS * HD floats.
// ---------------------------------------------------------------------------
__global__ void __launch_bounds__(HD) passA(const float* __restrict__ src,
                                            const float* __restrict__ ref) {
    extern __shared__ float sm[];
    float* S = sm;                      // [ROWS][HD]
    float* R = sm + ROWS * HD;          // [ROWS][HD]
    float* T = sm + 2 * ROWS * HD;      // [5][ROWS][HD]

    const int d  = threadIdx.x;
    const int b  = blockIdx.z;
    const int h  = blockIdx.y;
    const int w0 = blockIdx.x * WT;

    const size_t basebh = ((size_t)(b * HD + h)) * PLN;

    // Load 20 rows of s and r (reflect in w), coalesced along d.
    #pragma unroll
    for (int row = 0; row < ROWS; ++row) {
        int w = refl(w0 - 5 + row);
        size_t off = basebh + (size_t)w * HD + d;
        S[row * HD + d] = __ldg(src + off);
        R[row * HD + d] = __ldg(ref + off);
    }
    __syncthreads();

    // D-blur + field generation.
    for (int row = 0; row < ROWS; ++row) {
        float a0 = 0.f, a1 = 0.f, a2 = 0.f, a3 = 0.f, a4 = 0.f;
        #pragma unroll
        for (int k = 0; k < 11; ++k) {
            int dd = d - 5 + k;
            dd = (dd < 0) ? -dd : ((dd > HD - 1) ? (2 * (HD - 1) - dd) : dd);
            float s = S[row * HD + dd];
            float r = R[row * HD + dd];
            float t = GW[k] * s;
            float u = GW[k] * r;
            a0 += t;          // blur(s)
            a1 += u;          // blur(r)
            a2 += t * s;      // blur(s*s)
            a3 += u * r;      // blur(r*r)
            a4 += t * r;      // blur(s*r)
        }
        T[(0 * ROWS + row) * HD + d] = a0;
        T[(1 * ROWS + row) * HD + d] = a1;
        T[(2 * ROWS + row) * HD + d] = a2;
        T[(3 * ROWS + row) * HD + d] = a3;
        T[(4 * ROWS + row) * HD + d] = a4;
    }
    __syncthreads();

    // W-blur: thread owns column d; slide over 10 output w with a 20-value
    // register window per field (2 LDS per output instead of 11).
    #pragma unroll
    for (int f = 0; f < 5; ++f) {
        float v[ROWS];
        #pragma unroll
        for (int r2 = 0; r2 < ROWS; ++r2) v[r2] = T[(f * ROWS + r2) * HD + d];
        #pragma unroll
        for (int w = 0; w < WT; ++w) {
            float a = 0.f;
            #pragma unroll
            for (int k = 0; k < 11; ++k) a += GW[k] * v[w + k];
            g_buf[(size_t)f * NVOX + basebh + (size_t)(w0 + w) * HD + d] = a;
        }
    }
}

// ---------------------------------------------------------------------------
// Pass B: H-blur via fully-unrolled 11-plane register ring, then SSIM + reduce.
// Block: 160 threads (tid = d), grid (HD/HSEG, W, B). Each block covers one
// (b, w) column segment of HSEG h-planes.
// ---------------------------------------------------------------------------
__global__ void __launch_bounds__(HD) passB() {
    const int d  = threadIdx.x;
    const int b  = blockIdx.z;
    const int w  = blockIdx.y;
    const int h0 = blockIdx.x * HSEG;

    const size_t colbase = (size_t)b * VOL + (size_t)w * HD + d;

    const float* __restrict__ F0 = g_buf + 0ULL * NVOX;
    const float* __restrict__ F1 = g_buf + 1ULL * NVOX;
    const float* __restrict__ F2 = g_buf + 2ULL * NVOX;
    const float* __restrict__ F3 = g_buf + 3ULL * NVOX;
    const float* __restrict__ F4 = g_buf + 4ULL * NVOX;

    float win[5][11];

    // Warm-up: planes h0-5 .. h0+4 into slots 0..9. slot(q) = (q - h0 + 5) % 11
    #pragma unroll
    for (int j = 0; j < 10; ++j) {
        int q = refl(h0 - 5 + j);
        size_t off = colbase + (size_t)q * PLN;
        win[0][j] = __ldg(F0 + off);
        win[1][j] = __ldg(F1 + off);
        win[2][j] = __ldg(F2 + off);
        win[3][j] = __ldg(F3 + off);
        win[4][j] = __ldg(F4 + off);
    }

    float acc = 0.f;

    #pragma unroll
    for (int i = 0; i < HSEG; ++i) {
        // Load plane h0+i+5 (reflected) into slot (i+10)%11.
        {
            int q = refl(h0 + i + 5);
            size_t off = colbase + (size_t)q * PLN;
            int slot = (i + 10) % 11;
            win[0][slot] = __ldg(F0 + off);
            win[1][slot] = __ldg(F1 + off);
            win[2][slot] = __ldg(F2 + off);
            win[3][slot] = __ldg(F3 + off);
            win[4][slot] = __ldg(F4 + off);
        }
        // Output h = h0 + i uses planes h-5..h+5 at slots (i+k)%11.
        float mu1 = 0.f, mu2 = 0.f, m11 = 0.f, m22 = 0.f, m12 = 0.f;
        #pragma unroll
        for (int k = 0; k < 11; ++k) {
            int slot = (i + k) % 11;
            mu1 += GW[k] * win[0][slot];
            mu2 += GW[k] * win[1][slot];
            m11 += GW[k] * win[2][slot];
            m22 += GW[k] * win[3][slot];
            m12 += GW[k] * win[4][slot];
        }
        float mu1sq = mu1 * mu1;
        float mu2sq = mu2 * mu2;
        float mu12  = mu1 * mu2;
        float s1 = m11 - mu1sq;
        float s2 = m22 - mu2sq;
        float s12 = m12 - mu12;
        float num = (2.f * mu12 + C1f) * (2.f * s12 + C2f);
        float den = (mu1sq + mu2sq + C1f) * (s1 + s2 + C2f);
        acc += num / (den + EPSf);
    }

    // Reduce: 5 warps -> smem -> atomicAdd(double)
    float v = acc;
    #pragma unroll
    for (int o = 16; o > 0; o >>= 1) v += __shfl_down_sync(0xffffffffu, v, o);
    __shared__ float ws[5];
    if ((threadIdx.x & 31) == 0) ws[threadIdx.x >> 5] = v;
    __syncthreads();
    if (threadIdx.x == 0) {
        float s = ws[0] + ws[1] + ws[2] + ws[3] + ws[4];
        atomicAdd(&g_acc, (double)s);
    }
}

__global__ void zero_acc_kernel() { g_acc = 0.0; }

__global__ void finalize_kernel(float* out) {
    out[0] = (float)(1.0 - g_acc / (double)NVOX);
}

extern "C" void kernel_launch(void* const* d_in, const int* in_sizes, int n_in,
                              void* d_out, int out_size) {
    const float* src = (const float*)d_in[0];
    const float* ref = (const float*)d_in[1];
    float* out = (float*)d_out;

    const int smemA = (2 + 5) * ROWS * HD * (int)sizeof(float);  // 89600 B
    cudaFuncSetAttribute(passA, cudaFuncAttributeMaxDynamicSharedMemorySize, smemA);

    zero_acc_kernel<<<1, 1>>>();
    passA<<<dim3(HD / WT, HD, 2), HD, smemA>>>(src, ref);
    passB<<<dim3(HD / HSEG, HD, 2), HD>>>();
    finalize_kernel<<<1, 1>>>(out);
}